// round 2
// baseline (speedup 1.0000x reference)
#include <cuda_runtime.h>
#include <math.h>
#include <stdint.h>

// ---------------- problem constants ----------------
#define Bc   32
#define NRc  4096
#define DIN  384
#define DCTX 128
#define Hc   64
#define Ac   16
#define MTOT (Bc * NRc)

#define LOG_VAR2_C  (-4.6051701859880914f)
#define INV_VAR2_C  (100.0f)
#define STD2_C      (0.1f)

typedef unsigned long long u64;

// ---------------- device scratch ----------------
__device__ float g_embT[(size_t)Bc * Hc * NRc];   // [b][k][n]
__device__ float g_mse[Bc];
__device__ float g_kld[Bc];

// ---------------- f32x2 helpers ----------------
__device__ __forceinline__ void fma2(u64& d, u64 a, u64 b) {
    asm("fma.rn.f32x2 %0, %1, %2, %0;" : "+l"(d) : "l"(a), "l"(b));
}
__device__ __forceinline__ u64 splat2(float x) {
    u64 r; asm("mov.b64 %0, {%1, %1};" : "=l"(r) : "f"(x)); return r;
}
__device__ __forceinline__ float2 unpk(u64 v) {
    float2 r; asm("mov.b64 {%0, %1}, %2;" : "=f"(r.x), "=f"(r.y) : "l"(v)); return r;
}
__device__ __forceinline__ u64 pk(float x, float y) {
    u64 r; asm("mov.b64 %0, {%1, %2};" : "=l"(r) : "f"(x), "f"(y)); return r;
}

// 16 packed FMAs: acc[p][j] (row-pair p, col j) += a_pair[p] * (b[j],b[j])
__device__ __forceinline__ void mma16(u64 acc[4][4], const float* aptr, const u64* bptr) {
    ulonglong2 a01 = *reinterpret_cast<const ulonglong2*>(aptr);
    ulonglong2 a23 = *reinterpret_cast<const ulonglong2*>(aptr + 4);
    ulonglong2 b01 = *reinterpret_cast<const ulonglong2*>(bptr);
    ulonglong2 b23 = *reinterpret_cast<const ulonglong2*>(bptr + 2);
    u64 a[4] = {a01.x, a01.y, a23.x, a23.y};
    u64 b[4] = {b01.x, b01.y, b23.x, b23.y};
#pragma unroll
    for (int p = 0; p < 4; p++)
#pragma unroll
        for (int j = 0; j < 4; j++) fma2(acc[p][j], a[p], b[j]);
}

__device__ __forceinline__ void zero_acc(u64 acc[4][4]) {
#pragma unroll
    for (int p = 0; p < 4; p++)
#pragma unroll
        for (int j = 0; j < 4; j++) acc[p][j] = 0ULL;
}

// build (w,w) splat table for a 64x64 weight view with row stride `ld`
__device__ __forceinline__ void build_splat(u64* Wsp, const float* W, int ld, int tid) {
#pragma unroll
    for (int t = tid; t < 1024; t += 256) {
        int k  = t >> 4;
        int n4 = (t & 15) * 4;
        float4 w = *reinterpret_cast<const float4*>(W + (size_t)k * ld + n4);
        Wsp[k*64 + n4 + 0] = splat2(w.x);
        Wsp[k*64 + n4 + 1] = splat2(w.y);
        Wsp[k*64 + n4 + 2] = splat2(w.z);
        Wsp[k*64 + n4 + 3] = splat2(w.w);
    }
}

// ---------------- zero accumulators ----------------
__global__ void zero_kernel() {
    int t = threadIdx.x;
    if (t < Bc) { g_mse[t] = 0.0f; g_kld[t] = 0.0f; }
}

// ---------------- fused VAE kernel (FFMA2) ----------------
#define TS 132   // [k][m] tile stride (floats), 16B-aligned rows, low-conflict
#define VAE_SMEM_FLOATS (2112 + 2048 + 8448 + 8192 + 16 + 128)

__global__ __launch_bounds__(256, 2)
void vae_kernel(const float* __restrict__ roles, const float* __restrict__ eps,
                const float* __restrict__ W1,  const float* __restrict__ b1,
                const float* __restrict__ W21, const float* __restrict__ b21,
                const float* __restrict__ W22, const float* __restrict__ b22,
                const float* __restrict__ W3,  const float* __restrict__ b3,
                const float* __restrict__ W4,  const float* __restrict__ b4)
{
    extern __shared__ float sm[];
    float* As  = sm;                              // 16*132 = 2112
    u64*   Bsp = (u64*)(sm + 2112);               // 16*64 u64 = 2048 f
    float* Hs  = sm + 2112 + 2048;                // 64*132 = 8448
    u64*   Wsp = (u64*)(Hs + 8448);               // 64*64 u64 = 8192 f
    float* red = (float*)(Wsp + 4096);            // 16
    float* rns = red + 16;                        // 128

    const int tid  = threadIdx.x;
    const int tcol = tid & 15;
    const int trow = tid >> 4;
    const int m0   = trow * 8;
    const int c0   = tcol * 4;
    const int row0 = blockIdx.x * 128;
    const int b    = row0 >> 12;

    u64 acc[4][4];

    // ================= GEMM1: h = relu(roles @ W1 + b1) =================
    zero_acc(acc);
    for (int kt = 0; kt < DIN; kt += 16) {
        // A tile transposed into As[k][m]
#pragma unroll
        for (int q = 0; q < 2; q++) {
            int f  = tid + q * 256;
            int m  = f >> 2;
            int k4 = (f & 3) * 4;
            float4 v = *reinterpret_cast<const float4*>(
                roles + (size_t)(row0 + m) * DIN + kt + k4);
            As[(k4 + 0) * TS + m] = v.x;
            As[(k4 + 1) * TS + m] = v.y;
            As[(k4 + 2) * TS + m] = v.z;
            As[(k4 + 3) * TS + m] = v.w;
        }
        // W1 tile as splat pairs
        {
            int kk = tid >> 4;
            int n4 = (tid & 15) * 4;
            float4 w = *reinterpret_cast<const float4*>(W1 + (size_t)(kt + kk) * Hc + n4);
            Bsp[kk*64 + n4 + 0] = splat2(w.x);
            Bsp[kk*64 + n4 + 1] = splat2(w.y);
            Bsp[kk*64 + n4 + 2] = splat2(w.z);
            Bsp[kk*64 + n4 + 3] = splat2(w.w);
        }
        __syncthreads();
#pragma unroll 4
        for (int k = 0; k < 16; k++)
            mma16(acc, &As[k*TS + m0], &Bsp[k*64 + c0]);
        __syncthreads();
    }
    // epilogue: relu(+b1) -> Hs[h][m]
    {
        float4 bv = *reinterpret_cast<const float4*>(b1 + c0);
        float ba[4] = {bv.x, bv.y, bv.z, bv.w};
#pragma unroll
        for (int p = 0; p < 4; p++)
#pragma unroll
            for (int j = 0; j < 4; j++) {
                float2 v = unpk(acc[p][j]);
                v.x = fmaxf(v.x + ba[j], 0.0f);
                v.y = fmaxf(v.y + ba[j], 0.0f);
                *reinterpret_cast<u64*>(&Hs[(c0 + j) * TS + m0 + 2*p]) = pk(v.x, v.y);
            }
    }
    build_splat(Wsp, W22, 64, tid);
    __syncthreads();

    float kacc = 0.0f;
    u64 srp[4][4];

    // ================= log_var = h@W22 + b22 =================
    zero_acc(acc);
#pragma unroll 4
    for (int k = 0; k < 64; k++)
        mma16(acc, &Hs[k*TS + m0], &Wsp[k*64 + c0]);
    {
        float4 bv = *reinterpret_cast<const float4*>(b22 + c0);
        float ba[4] = {bv.x, bv.y, bv.z, bv.w};
#pragma unroll
        for (int p = 0; p < 4; p++)
#pragma unroll
            for (int j = 0; j < 4; j++) {
                float2 lv = unpk(acc[p][j]);
                float lx = lv.x + ba[j], ly = lv.y + ba[j];
                float ex = expf(lx),  ey = expf(ly);
                kacc += (1.0f - LOG_VAR2_C + lx - ex * INV_VAR2_C);
                kacc += (1.0f - LOG_VAR2_C + ly - ey * INV_VAR2_C);
                srp[p][j] = pk(sqrtf(ex) * STD2_C, sqrtf(ey) * STD2_C);
            }
    }
    __syncthreads();
    build_splat(Wsp, W21, 64, tid);
    __syncthreads();

    // ================= mu = h@W21 + b21 ; z = mu + eps*s =================
    zero_acc(acc);
#pragma unroll 4
    for (int k = 0; k < 64; k++)
        mma16(acc, &Hs[k*TS + m0], &Wsp[k*64 + c0]);
    {
        float4 bv = *reinterpret_cast<const float4*>(b21 + c0);
        float ba[4] = {bv.x, bv.y, bv.z, bv.w};
#pragma unroll
        for (int p = 0; p < 4; p++) {
            float4 e0 = *reinterpret_cast<const float4*>(
                eps + (size_t)(row0 + m0 + 2*p) * Hc + c0);
            float4 e1 = *reinterpret_cast<const float4*>(
                eps + (size_t)(row0 + m0 + 2*p + 1) * Hc + c0);
            float e0a[4] = {e0.x, e0.y, e0.z, e0.w};
            float e1a[4] = {e1.x, e1.y, e1.z, e1.w};
#pragma unroll
            for (int j = 0; j < 4; j++) {
                float2 mu = unpk(acc[p][j]);
                float mx = mu.x + ba[j], my = mu.y + ba[j];
                kacc -= (mx*mx + my*my) * INV_VAR2_C;
                float2 s2 = unpk(srp[p][j]);
                acc[p][j] = pk(fmaf(e0a[j], s2.x, mx), fmaf(e1a[j], s2.y, my));
            }
        }
    }
    __syncthreads();               // all reads of Hs(h) done
    // write z -> Hs (already packed row-pairs)
#pragma unroll
    for (int p = 0; p < 4; p++)
#pragma unroll
        for (int j = 0; j < 4; j++)
            *reinterpret_cast<u64*>(&Hs[(c0 + j) * TS + m0 + 2*p]) = acc[p][j];
    build_splat(Wsp, W3, 64, tid);
    __syncthreads();

    // ================= l2 norms, emb store (transposed) =================
    if (tid < 128) {
        float ss = 0.0f;
#pragma unroll
        for (int k = 0; k < 64; k++) { float v = Hs[k*TS + tid]; ss += v * v; }
        rns[tid] = 1.0f / fmaxf(sqrtf(ss), 1e-12f);
    }
    __syncthreads();
    {
        const int nloc0 = row0 & (NRc - 1);
        for (int t = tid; t < 128 * 64; t += 256) {
            int k = t >> 7;
            int r = t & 127;
            g_embT[((size_t)b * Hc + k) * NRc + nloc0 + r] = Hs[k*TS + r] * rns[r];
        }
    }

    // ================= g = relu(z@W3 + b3) =================
    zero_acc(acc);
#pragma unroll 4
    for (int k = 0; k < 64; k++)
        mma16(acc, &Hs[k*TS + m0], &Wsp[k*64 + c0]);
    {
        float4 bv = *reinterpret_cast<const float4*>(b3 + c0);
        float ba[4] = {bv.x, bv.y, bv.z, bv.w};
#pragma unroll
        for (int p = 0; p < 4; p++)
#pragma unroll
            for (int j = 0; j < 4; j++) {
                float2 v = unpk(acc[p][j]);
                acc[p][j] = pk(fmaxf(v.x + ba[j], 0.0f), fmaxf(v.y + ba[j], 0.0f));
            }
    }
    __syncthreads();               // all reads of Hs(z) + embT reads done
#pragma unroll
    for (int p = 0; p < 4; p++)
#pragma unroll
        for (int j = 0; j < 4; j++)
            *reinterpret_cast<u64*>(&Hs[(c0 + j) * TS + m0 + 2*p]) = acc[p][j];

    // ================= mse: x_hat = g@W4 + b4 vs roles =================
    float msacc = 0.0f;
    for (int ch = 0; ch < 6; ch++) {
        __syncthreads();           // prev Wsp reads / Hs(g) writes done
        build_splat(Wsp, W4 + ch * 64, DIN, tid);
        __syncthreads();
        zero_acc(acc);
#pragma unroll 4
        for (int k = 0; k < 64; k++)
            mma16(acc, &Hs[k*TS + m0], &Wsp[k*64 + c0]);
        {
            float4 bv = *reinterpret_cast<const float4*>(b4 + ch * 64 + c0);
            float ba[4] = {bv.x, bv.y, bv.z, bv.w};
#pragma unroll
            for (int p = 0; p < 4; p++) {
                float4 r0 = *reinterpret_cast<const float4*>(
                    roles + (size_t)(row0 + m0 + 2*p) * DIN + ch * 64 + c0);
                float4 r1 = *reinterpret_cast<const float4*>(
                    roles + (size_t)(row0 + m0 + 2*p + 1) * DIN + ch * 64 + c0);
                float r0a[4] = {r0.x, r0.y, r0.z, r0.w};
                float r1a[4] = {r1.x, r1.y, r1.z, r1.w};
#pragma unroll
                for (int j = 0; j < 4; j++) {
                    float2 v = unpk(acc[p][j]);
                    float d0 = v.x + ba[j] - r0a[j];
                    float d1 = v.y + ba[j] - r1a[j];
                    msacc += d0*d0 + d1*d1;
                }
            }
        }
    }

    // ================= block reduce kld / mse =================
    float ks = kacc, ms = msacc;
#pragma unroll
    for (int off = 16; off > 0; off >>= 1) {
        ks += __shfl_xor_sync(0xffffffffu, ks, off);
        ms += __shfl_xor_sync(0xffffffffu, ms, off);
    }
    __syncthreads();
    if ((tid & 31) == 0) { red[tid >> 5] = ks; red[8 + (tid >> 5)] = ms; }
    __syncthreads();
    if (tid == 0) {
        float kt = 0.0f, mt = 0.0f;
#pragma unroll
        for (int w = 0; w < 8; w++) { kt += red[w]; mt += red[8 + w]; }
        atomicAdd(&g_kld[b], kt);
        atomicAdd(&g_mse[b], mt);
    }
}

// ---------------- vae loss finalize ----------------
__global__ void finalize_kernel(float* __restrict__ out) {
    if (threadIdx.x == 0) {
        float v = 0.0f;
        for (int b = 0; b < Bc; b++) {
            float mse = g_mse[b] * (1.0f / ((float)NRc * (float)DIN));
            float kld = (-0.5f / ((float)NRc * (float)Hc)) * g_kld[b];
            v += mse + kld;
        }
        out[Bc*Ac + Bc + Bc*Hc] = v / (float)Bc;
    }
}

// ---------------- cluster helpers ----------------
__device__ __forceinline__ uint32_t s2u(const void* p) {
    uint32_t a;
    asm("{ .reg .u64 t; cvta.to.shared.u64 t, %1; cvt.u32.u64 %0, t; }" : "=r"(a) : "l"(p));
    return a;
}
__device__ __forceinline__ void st_cluster_f32(uint32_t addr, uint32_t rank, float v) {
    uint32_t ra;
    asm("mapa.shared::cluster.u32 %0, %1, %2;" : "=r"(ra) : "r"(addr), "r"(rank));
    asm volatile("st.shared::cluster.f32 [%0], %1;" :: "r"(ra), "f"(v) : "memory");
}
__device__ __forceinline__ void st_cluster_u32(uint32_t addr, uint32_t rank, uint32_t v) {
    uint32_t ra;
    asm("mapa.shared::cluster.u32 %0, %1, %2;" : "=r"(ra) : "r"(addr), "r"(rank));
    asm volatile("st.shared::cluster.u32 [%0], %1;" :: "r"(ra), "r"(v) : "memory");
}
#define CLUSTER_SYNC() do { \
    asm volatile("barrier.cluster.arrive.aligned;" ::: "memory"); \
    asm volatile("barrier.cluster.wait.aligned;"   ::: "memory"); } while (0)

// ---------------- cluster-parallel selection scan ----------------
#define CL 4
#define SCAN_THREADS 256
#define ROWS_PER_CTA (NRc / CL)       // 1024
#define SCAN_SMEM_FLOATS (12288 + 128 + 64*4 + 256 + 8 + 8 + 8 + 4 + 4 + 4)

__global__ __launch_bounds__(SCAN_THREADS, 1) __cluster_dims__(CL, 1, 1)
void scan_kernel(const float* __restrict__ contexts, const float* __restrict__ rand_vals,
                 const float* __restrict__ Wc, const float* __restrict__ bc,
                 const float* __restrict__ init_emb, float* __restrict__ out)
{
    extern __shared__ float sm[];
    float* Wcs   = sm;                 // 192*64
    float* ctxs  = Wcs + 12288;        // 128
    float* hist  = ctxs + 128;         // 64
    float* cur   = hist + 64;          // 64
    float* tmp   = cur + 64;           // 64
    float* cvec  = tmp + 64;           // 64
    float* cpart = cvec + 64;          // 256
    float* wred  = cpart + 256;        // 8
    float* wexc  = wred + 8;           // 8
    float* scal  = wexc + 8;           // 8: [0]=lp [1]=mean [2]=invstd [3]=cnorm [4]=S_local
    float* exchS = scal + 8;           // 4
    int*   exchC = (int*)(exchS + 4);  // 4
    int*   seli  = exchC + 4;          // 1

    const int b    = blockIdx.x >> 2;
    const int rank = blockIdx.x & 3;
    const int tid  = threadIdx.x;
    const int lane = tid & 31;
    const int wid  = tid >> 5;

    const uint32_t exchS_addr = s2u(exchS);
    const uint32_t exchC_addr = s2u(exchC);

    for (int t = tid; t < 12288 / 4; t += SCAN_THREADS)
        *reinterpret_cast<float4*>(&Wcs[t*4]) = *reinterpret_cast<const float4*>(Wc + t*4);
    if (tid < 128) ctxs[tid] = contexts[b * DCTX + tid];
    if (tid < 64)  { float iv = init_emb[tid]; hist[tid] = iv; cur[tid] = iv; }
    if (tid == 0)  scal[0] = 0.0f;
    __syncthreads();
    CLUSTER_SYNC();                    // all cluster smem live before DSMEM traffic

    const float* embT = g_embT + (size_t)b * Hc * NRc;
    const float* eb   = embT + rank * ROWS_PER_CTA + 4 * tid;

    for (int step = 0; step < Ac; step++) {
        // ---- hist = layernorm(hist + cur)
        if (tid < 64) tmp[tid] = hist[tid] + cur[tid];
        if (tid == 0) seli[0] = 0x7fffffff;
        __syncthreads();
        if (wid == 0) {
            float x0 = tmp[lane], x1 = tmp[lane + 32];
            float s = x0 + x1;
#pragma unroll
            for (int off = 16; off > 0; off >>= 1) s += __shfl_xor_sync(0xffffffffu, s, off);
            float mean = s * (1.0f / 64.0f);
            float d0 = x0 - mean, d1 = x1 - mean;
            float vs = d0*d0 + d1*d1;
#pragma unroll
            for (int off = 16; off > 0; off >>= 1) vs += __shfl_xor_sync(0xffffffffu, vs, off);
            if (lane == 0) {
                scal[1] = mean;
                scal[2] = 1.0f / sqrtf(vs * (1.0f / 64.0f) + 1e-5f);
            }
        }
        __syncthreads();
        if (tid < 64) hist[tid] = (tmp[tid] - scal[1]) * scal[2];
        __syncthreads();

        // ---- c = concat(ctx, hist) @ Wc + bc (4-way split), then normalize
        {
            int col = tid & 63, part = tid >> 6;
            int i0 = part * 48;
            float s = 0.0f;
#pragma unroll 8
            for (int i = i0; i < i0 + 48; i++) {
                float x = (i < 128) ? ctxs[i] : hist[i - 128];
                s = fmaf(x, Wcs[i*64 + col], s);
            }
            cpart[part * 64 + col] = s;
        }
        __syncthreads();
        if (tid < 64)
            cvec[tid] = bc[tid] + cpart[tid] + cpart[64+tid] + cpart[128+tid] + cpart[192+tid];
        __syncthreads();
        if (wid == 0) {
            float c0 = cvec[lane], c1 = cvec[lane + 32];
            float ss = c0*c0 + c1*c1;
#pragma unroll
            for (int off = 16; off > 0; off >>= 1) ss += __shfl_xor_sync(0xffffffffu, ss, off);
            if (lane == 0) scal[3] = 1.0f / fmaxf(sqrtf(ss), 1e-12f);
        }
        __syncthreads();
        if (tid < 64) cvec[tid] *= scal[3];
        __syncthreads();

        // ---- unnormalized scores e = exp(emb@c)  (|score|<=1: no max pass needed)
        float sx = 0.f, sy = 0.f, sz = 0.f, sw = 0.f;
#pragma unroll 8
        for (int k = 0; k < 64; k++) {
            float4 v = *reinterpret_cast<const float4*>(eb + (size_t)k * NRc);
            float ck = cvec[k];
            sx = fmaf(v.x, ck, sx); sy = fmaf(v.y, ck, sy);
            sz = fmaf(v.z, ck, sz); sw = fmaf(v.w, ck, sw);
        }
        float e0 = expf(sx), e1 = expf(sy), e2 = expf(sz), e3 = expf(sw);
        float t4 = (e0 + e1) + (e2 + e3);

        // ---- intra-CTA prefix of per-thread totals
        float incl = t4;
#pragma unroll
        for (int off = 1; off < 32; off <<= 1) {
            float n = __shfl_up_sync(0xffffffffu, incl, off);
            if (lane >= off) incl += n;
        }
        if (lane == 31) wred[wid] = incl;
        __syncthreads();
        if (tid == 0) {
            float s = 0.0f;
#pragma unroll
            for (int w = 0; w < 8; w++) { float v = wred[w]; wexc[w] = s; s += v; }
            scal[4] = s;
        }
        __syncthreads();
        float S_local  = scal[4];
        float excl_thr = wexc[wid] + (incl - t4);

        // ---- cluster: share local sums
        if (tid < CL) st_cluster_f32(exchS_addr + (uint32_t)rank * 4u, (uint32_t)tid, S_local);
        CLUSTER_SYNC();
        float S_tot = 0.0f, pre = 0.0f;
#pragma unroll
        for (int r = 0; r < CL; r++) {
            float v = exchS[r];
            if (r < rank) pre += v;
            S_tot += v;
        }

        // ---- selection: first global index with cumsum(e) > r * S_tot
        float T = rand_vals[b * Ac + step] * S_tot;
        float base = pre + excl_thr;
        int cand = 0x7fffffff;
        int gr = rank * ROWS_PER_CTA + tid * 4;
        if      (base + e0 > T)                 cand = gr;
        else if (base + e0 + e1 > T)            cand = gr + 1;
        else if (base + e0 + e1 + e2 > T)       cand = gr + 2;
        else if (base + t4 > T)                 cand = gr + 3;
        if (cand != 0x7fffffff) atomicMin(seli, cand);
        __syncthreads();
        int lc = seli[0];
        if (tid < CL) st_cluster_u32(exchC_addr + (uint32_t)rank * 4u, (uint32_t)tid, (uint32_t)lc);
        CLUSTER_SYNC();
        int sel = 0x7fffffff;
#pragma unroll
        for (int r = 0; r < CL; r++) sel = min(sel, exchC[r]);
        if (sel == 0x7fffffff) sel = 0;

        // ---- cur = emb[sel]; lp += score_sel - log(S_tot)
        if (tid < 64) cur[tid] = embT[(size_t)tid * NRc + sel];
        __syncthreads();
        if (wid == 0) {
            float d = cur[lane] * cvec[lane] + cur[lane + 32] * cvec[lane + 32];
#pragma unroll
            for (int off = 16; off > 0; off >>= 1) d += __shfl_xor_sync(0xffffffffu, d, off);
            if (lane == 0) scal[0] += d - logf(S_tot);
        }
        if (rank == 0 && tid == 0) out[b * Ac + step] = (float)sel;
        __syncthreads();
    }

    if (rank == 0 && tid == 0) out[Bc*Ac + b] = scal[0];
    if (rank == 0 && tid < 64) out[Bc*Ac + Bc + b*Hc + tid] = hist[tid];
    CLUSTER_SYNC();
}

// ---------------- launcher ----------------
extern "C" void kernel_launch(void* const* d_in, const int* in_sizes, int n_in,
                              void* d_out, int out_size) {
    const float* roles     = (const float*)d_in[0];
    const float* contexts  = (const float*)d_in[1];
    const float* eps       = (const float*)d_in[2];
    const float* rand_vals = (const float*)d_in[3];
    const float* W1  = (const float*)d_in[5];
    const float* b1  = (const float*)d_in[6];
    const float* W21 = (const float*)d_in[7];
    const float* b21 = (const float*)d_in[8];
    const float* W22 = (const float*)d_in[9];
    const float* b22 = (const float*)d_in[10];
    const float* W3  = (const float*)d_in[11];
    const float* b3  = (const float*)d_in[12];
    const float* W4  = (const float*)d_in[13];
    const float* b4  = (const float*)d_in[14];
    const float* Wc  = (const float*)d_in[15];
    const float* bc  = (const float*)d_in[16];
    const float* init_emb = (const float*)d_in[17];
    float* out = (float*)d_out;

    const int vae_smem  = VAE_SMEM_FLOATS  * (int)sizeof(float);
    const int scan_smem = SCAN_SMEM_FLOATS * (int)sizeof(float);
    cudaFuncSetAttribute(vae_kernel,  cudaFuncAttributeMaxDynamicSharedMemorySize, vae_smem);
    cudaFuncSetAttribute(scan_kernel, cudaFuncAttributeMaxDynamicSharedMemorySize, scan_smem);

    zero_kernel<<<1, 32>>>();
    vae_kernel<<<MTOT / 128, 256, vae_smem>>>(roles, eps, W1, b1, W21, b21,
                                              W22, b22, W3, b3, W4, b4);
    finalize_kernel<<<1, 1>>>(out);
    scan_kernel<<<Bc * CL, SCAN_THREADS, scan_smem>>>(contexts, rand_vals, Wc, bc,
                                                      init_emb, out);
}

// round 3
// speedup vs baseline: 1.4702x; 1.4702x over previous
#include <cuda_runtime.h>
#include <math.h>
#include <stdint.h>

// ---------------- problem constants ----------------
#define Bc   32
#define NRc  4096
#define DIN  384
#define DCTX 128
#define Hc   64
#define Ac   16
#define MTOT (Bc * NRc)

#define LOG_VAR2_C  (-4.6051701859880914f)
#define INV_VAR2_C  (100.0f)
#define STD2_C      (0.1f)

// ---------------- device scratch ----------------
__device__ float g_embT[(size_t)Bc * Hc * NRc];   // [b][k][n]
__device__ float g_mse[Bc];
__device__ float g_kld[Bc];

// ---------------- zero accumulators ----------------
__global__ void zero_kernel() {
    int t = threadIdx.x;
    if (t < Bc) { g_mse[t] = 0.0f; g_kld[t] = 0.0f; }
}

// ---------------- fused VAE kernel (round-1 scalar version, proven ~390us) ----------------
#define VAE_SMEM_FLOATS (16*128 + 16*64 + 128*65 + 64*64 + 64 + 128)

__global__ __launch_bounds__(256, 2)
void vae_kernel(const float* __restrict__ roles, const float* __restrict__ eps,
                const float* __restrict__ W1,  const float* __restrict__ b1,
                const float* __restrict__ W21, const float* __restrict__ b21,
                const float* __restrict__ W22, const float* __restrict__ b22,
                const float* __restrict__ W3,  const float* __restrict__ b3,
                const float* __restrict__ W4,  const float* __restrict__ b4)
{
    extern __shared__ float sm[];
    float* As  = sm;
    float* Bs  = As + 16*128;
    float* Hs  = Bs + 16*64;
    float* Ws  = Hs + 128*65;
    float* red = Ws + 64*64;
    float* rns = red + 64;

    const int tid  = threadIdx.x;
    const int tcol = tid & 15;
    const int trow = tid >> 4;
    const int row0 = blockIdx.x * 128;
    const int b    = row0 >> 12;

    float acc[8][4];

    // ================= GEMM1: h = relu(roles @ W1 + b1) =================
#pragma unroll
    for (int i = 0; i < 8; i++)
#pragma unroll
        for (int j = 0; j < 4; j++) acc[i][j] = 0.0f;

    for (int kt = 0; kt < DIN; kt += 16) {
#pragma unroll
        for (int q = 0; q < 2; q++) {
            int f  = tid + q * 256;
            int m  = f >> 2;
            int k4 = (f & 3) * 4;
            float4 v = *reinterpret_cast<const float4*>(
                roles + (size_t)(row0 + m) * DIN + kt + k4);
            As[(k4 + 0) * 128 + m] = v.x;
            As[(k4 + 1) * 128 + m] = v.y;
            As[(k4 + 2) * 128 + m] = v.z;
            As[(k4 + 3) * 128 + m] = v.w;
        }
        {
            int k  = tid >> 4;
            int j4 = (tid & 15) * 4;
            *reinterpret_cast<float4*>(&Bs[k * 64 + j4]) =
                *reinterpret_cast<const float4*>(W1 + (size_t)(kt + k) * Hc + j4);
        }
        __syncthreads();
#pragma unroll
        for (int k = 0; k < 16; k++) {
            float a[8];
            *reinterpret_cast<float4*>(&a[0]) = *reinterpret_cast<float4*>(&As[k*128 + trow*8]);
            *reinterpret_cast<float4*>(&a[4]) = *reinterpret_cast<float4*>(&As[k*128 + trow*8 + 4]);
            float4 bb = *reinterpret_cast<float4*>(&Bs[k*64 + tcol*4]);
#pragma unroll
            for (int i = 0; i < 8; i++) {
                acc[i][0] += a[i] * bb.x;
                acc[i][1] += a[i] * bb.y;
                acc[i][2] += a[i] * bb.z;
                acc[i][3] += a[i] * bb.w;
            }
        }
        __syncthreads();
    }
    {
        float4 bv = *reinterpret_cast<const float4*>(b1 + tcol * 4);
#pragma unroll
        for (int i = 0; i < 8; i++) {
            int r = trow * 8 + i;
            Hs[r*65 + tcol*4 + 0] = fmaxf(acc[i][0] + bv.x, 0.0f);
            Hs[r*65 + tcol*4 + 1] = fmaxf(acc[i][1] + bv.y, 0.0f);
            Hs[r*65 + tcol*4 + 2] = fmaxf(acc[i][2] + bv.z, 0.0f);
            Hs[r*65 + tcol*4 + 3] = fmaxf(acc[i][3] + bv.w, 0.0f);
        }
    }
    for (int t = tid; t < 1024; t += 256)
        *reinterpret_cast<float4*>(&Ws[t*4]) = *reinterpret_cast<const float4*>(W22 + t*4);
    __syncthreads();

    float kacc = 0.0f;
    float sreg[8][4];

    // ================= log_var = h@W22 + b22 =================
#pragma unroll
    for (int i = 0; i < 8; i++)
#pragma unroll
        for (int j = 0; j < 4; j++) acc[i][j] = 0.0f;
#pragma unroll 8
    for (int k = 0; k < 64; k++) {
        float a[8];
#pragma unroll
        for (int i = 0; i < 8; i++) a[i] = Hs[(trow*8 + i)*65 + k];
        float4 bb = *reinterpret_cast<float4*>(&Ws[k*64 + tcol*4]);
#pragma unroll
        for (int i = 0; i < 8; i++) {
            acc[i][0] += a[i]*bb.x; acc[i][1] += a[i]*bb.y;
            acc[i][2] += a[i]*bb.z; acc[i][3] += a[i]*bb.w;
        }
    }
    {
        float4 bv = *reinterpret_cast<const float4*>(b22 + tcol * 4);
#pragma unroll
        for (int i = 0; i < 8; i++) {
            float bvv[4] = {bv.x, bv.y, bv.z, bv.w};
#pragma unroll
            for (int j = 0; j < 4; j++) {
                float lv = acc[i][j] + bvv[j];
                float ex = expf(lv);
                kacc += (1.0f - LOG_VAR2_C + lv - ex * INV_VAR2_C);
                sreg[i][j] = expf(0.5f * lv) * STD2_C;
            }
        }
    }
    __syncthreads();
    for (int t = tid; t < 1024; t += 256)
        *reinterpret_cast<float4*>(&Ws[t*4]) = *reinterpret_cast<const float4*>(W21 + t*4);
    __syncthreads();

    // ================= mu = h@W21 + b21 ; z = mu + eps*s =================
#pragma unroll
    for (int i = 0; i < 8; i++)
#pragma unroll
        for (int j = 0; j < 4; j++) acc[i][j] = 0.0f;
#pragma unroll 8
    for (int k = 0; k < 64; k++) {
        float a[8];
#pragma unroll
        for (int i = 0; i < 8; i++) a[i] = Hs[(trow*8 + i)*65 + k];
        float4 bb = *reinterpret_cast<float4*>(&Ws[k*64 + tcol*4]);
#pragma unroll
        for (int i = 0; i < 8; i++) {
            acc[i][0] += a[i]*bb.x; acc[i][1] += a[i]*bb.y;
            acc[i][2] += a[i]*bb.z; acc[i][3] += a[i]*bb.w;
        }
    }
    {
        float4 bv = *reinterpret_cast<const float4*>(b21 + tcol * 4);
        float bvv[4] = {bv.x, bv.y, bv.z, bv.w};
#pragma unroll
        for (int i = 0; i < 8; i++) {
            float4 ev = *reinterpret_cast<const float4*>(
                eps + (size_t)(row0 + trow*8 + i) * Hc + tcol * 4);
            float evv[4] = {ev.x, ev.y, ev.z, ev.w};
#pragma unroll
            for (int j = 0; j < 4; j++) {
                float mu = acc[i][j] + bvv[j];
                kacc -= mu * mu * INV_VAR2_C;
                acc[i][j] = mu + evv[j] * sreg[i][j];
            }
        }
    }
    __syncthreads();
#pragma unroll
    for (int i = 0; i < 8; i++) {
        int r = trow * 8 + i;
        Hs[r*65 + tcol*4 + 0] = acc[i][0];
        Hs[r*65 + tcol*4 + 1] = acc[i][1];
        Hs[r*65 + tcol*4 + 2] = acc[i][2];
        Hs[r*65 + tcol*4 + 3] = acc[i][3];
    }
    for (int t = tid; t < 1024; t += 256)
        *reinterpret_cast<float4*>(&Ws[t*4]) = *reinterpret_cast<const float4*>(W3 + t*4);
    __syncthreads();

    // ================= role_emb = l2norm(z), stored transposed =================
    if (tid < 128) {
        float ss = 0.0f;
#pragma unroll
        for (int k = 0; k < 64; k++) { float v = Hs[tid*65 + k]; ss += v * v; }
        rns[tid] = 1.0f / fmaxf(sqrtf(ss), 1e-12f);
    }
    __syncthreads();
    {
        const int nloc0 = row0 & (NRc - 1);
        for (int t = tid; t < 128 * 64; t += 256) {
            int k = t >> 7;
            int r = t & 127;
            g_embT[((size_t)b * Hc + k) * NRc + nloc0 + r] = Hs[r*65 + k] * rns[r];
        }
    }

    // ================= g = relu(z@W3 + b3) =================
#pragma unroll
    for (int i = 0; i < 8; i++)
#pragma unroll
        for (int j = 0; j < 4; j++) acc[i][j] = 0.0f;
#pragma unroll 8
    for (int k = 0; k < 64; k++) {
        float a[8];
#pragma unroll
        for (int i = 0; i < 8; i++) a[i] = Hs[(trow*8 + i)*65 + k];
        float4 bb = *reinterpret_cast<float4*>(&Ws[k*64 + tcol*4]);
#pragma unroll
        for (int i = 0; i < 8; i++) {
            acc[i][0] += a[i]*bb.x; acc[i][1] += a[i]*bb.y;
            acc[i][2] += a[i]*bb.z; acc[i][3] += a[i]*bb.w;
        }
    }
    {
        float4 bv = *reinterpret_cast<const float4*>(b3 + tcol * 4);
        float bvv[4] = {bv.x, bv.y, bv.z, bv.w};
#pragma unroll
        for (int i = 0; i < 8; i++)
#pragma unroll
            for (int j = 0; j < 4; j++)
                acc[i][j] = fmaxf(acc[i][j] + bvv[j], 0.0f);
    }
    __syncthreads();
#pragma unroll
    for (int i = 0; i < 8; i++) {
        int r = trow * 8 + i;
        Hs[r*65 + tcol*4 + 0] = acc[i][0];
        Hs[r*65 + tcol*4 + 1] = acc[i][1];
        Hs[r*65 + tcol*4 + 2] = acc[i][2];
        Hs[r*65 + tcol*4 + 3] = acc[i][3];
    }

    // ================= mse: x_hat = g@W4 + b4 vs roles =================
    float msacc = 0.0f;
    for (int ch = 0; ch < 6; ch++) {
        for (int t = tid; t < 1024; t += 256) {
            int k  = t >> 4;
            int j4 = (t & 15) * 4;
            *reinterpret_cast<float4*>(&Ws[k*64 + j4]) =
                *reinterpret_cast<const float4*>(W4 + (size_t)k * DIN + ch * 64 + j4);
        }
        __syncthreads();
#pragma unroll
        for (int i = 0; i < 8; i++)
#pragma unroll
            for (int j = 0; j < 4; j++) acc[i][j] = 0.0f;
#pragma unroll 8
        for (int k = 0; k < 64; k++) {
            float a[8];
#pragma unroll
            for (int i = 0; i < 8; i++) a[i] = Hs[(trow*8 + i)*65 + k];
            float4 bb = *reinterpret_cast<float4*>(&Ws[k*64 + tcol*4]);
#pragma unroll
            for (int i = 0; i < 8; i++) {
                acc[i][0] += a[i]*bb.x; acc[i][1] += a[i]*bb.y;
                acc[i][2] += a[i]*bb.z; acc[i][3] += a[i]*bb.w;
            }
        }
        {
            float4 bv = *reinterpret_cast<const float4*>(b4 + ch * 64 + tcol * 4);
            float bvv[4] = {bv.x, bv.y, bv.z, bv.w};
#pragma unroll
            for (int i = 0; i < 8; i++) {
                float4 rv = *reinterpret_cast<const float4*>(
                    roles + (size_t)(row0 + trow*8 + i) * DIN + ch * 64 + tcol * 4);
                float rvv[4] = {rv.x, rv.y, rv.z, rv.w};
#pragma unroll
                for (int j = 0; j < 4; j++) {
                    float d = acc[i][j] + bvv[j] - rvv[j];
                    msacc += d * d;
                }
            }
        }
        __syncthreads();
    }

    float ks = kacc, ms = msacc;
#pragma unroll
    for (int off = 16; off > 0; off >>= 1) {
        ks += __shfl_xor_sync(0xffffffffu, ks, off);
        ms += __shfl_xor_sync(0xffffffffu, ms, off);
    }
    if ((tid & 31) == 0) { red[tid >> 5] = ks; red[8 + (tid >> 5)] = ms; }
    __syncthreads();
    if (tid == 0) {
        float kt = 0.0f, mt = 0.0f;
#pragma unroll
        for (int w = 0; w < 8; w++) { kt += red[w]; mt += red[8 + w]; }
        atomicAdd(&g_kld[b], kt);
        atomicAdd(&g_mse[b], mt);
    }
}

// ---------------- vae loss finalize ----------------
__global__ void finalize_kernel(float* __restrict__ out) {
    if (threadIdx.x == 0) {
        float v = 0.0f;
        for (int b = 0; b < Bc; b++) {
            float mse = g_mse[b] * (1.0f / ((float)NRc * (float)DIN));
            float kld = (-0.5f / ((float)NRc * (float)Hc)) * g_kld[b];
            v += mse + kld;
        }
        out[Bc*Ac + Bc + Bc*Hc] = v / (float)Bc;
    }
}

// ---------------- cluster helpers ----------------
__device__ __forceinline__ uint32_t s2u(const void* p) {
    uint32_t a;
    asm("{ .reg .u64 t; cvta.to.shared.u64 t, %1; cvt.u32.u64 %0, t; }" : "=r"(a) : "l"(p));
    return a;
}
__device__ __forceinline__ void st_cluster_f32(uint32_t addr, uint32_t rank, float v) {
    uint32_t ra;
    asm("mapa.shared::cluster.u32 %0, %1, %2;" : "=r"(ra) : "r"(addr), "r"(rank));
    asm volatile("st.shared::cluster.f32 [%0], %1;" :: "r"(ra), "f"(v) : "memory");
}
__device__ __forceinline__ void st_cluster_u32(uint32_t addr, uint32_t rank, uint32_t v) {
    uint32_t ra;
    asm("mapa.shared::cluster.u32 %0, %1, %2;" : "=r"(ra) : "r"(addr), "r"(rank));
    asm volatile("st.shared::cluster.u32 [%0], %1;" :: "r"(ra), "r"(v) : "memory");
}
#define CLUSTER_SYNC() do { \
    asm volatile("barrier.cluster.arrive.aligned;" ::: "memory"); \
    asm volatile("barrier.cluster.wait.aligned;"   ::: "memory"); } while (0)

// ---------------- cluster-parallel selection scan ----------------
// CL=4 CTAs per batch item, 512 threads each; thread owns 2 consecutive rows.
// First NCACHE columns of the CTA's 1024-row slice live in smem (loaded once);
// remainder streams from L2 each step.
#define CL 4
#define STH 512
#define RPC (NRc / CL)          // 1024 rows per CTA
#define NCACHE 640              // rows cached in smem (warp-aligned: 640/2=320=warp 10)
#define SCAN_SMEM_FLOATS (12288 + 64*NCACHE + 128 + 64 + 4*64 + 512 + 16 + 16 + 8 + 4 + 4 + 4)

__global__ __launch_bounds__(STH, 1) __cluster_dims__(CL, 1, 1)
void scan_kernel(const float* __restrict__ contexts, const float* __restrict__ rand_vals,
                 const float* __restrict__ Wc, const float* __restrict__ bc,
                 const float* __restrict__ init_emb, float* __restrict__ out)
{
    extern __shared__ float sm[];
    float* Wcs   = sm;                   // 12288
    float* embc  = Wcs + 12288;          // 64*NCACHE
    float* ctxs  = embc + 64*NCACHE;     // 128
    float* bcs   = ctxs + 128;           // 64
    float* hist  = bcs + 64;             // 64
    float* cur   = hist + 64;            // 64
    float* tmp   = cur + 64;             // 64
    float* cvec  = tmp + 64;             // 64
    float* cpart = cvec + 64;            // 512
    float* wred  = cpart + 512;          // 16
    float* wexc  = wred + 16;            // 16
    float* scal  = wexc + 16;            // 8: [0]=lp [1]=mean [2]=invstd [3]=cnorm [4]=S_local
    float* exchS = scal + 8;             // 4
    int*   exchC = (int*)(exchS + 4);    // 4
    int*   seli  = exchC + 4;            // 1

    const int b    = blockIdx.x >> 2;
    const int rank = blockIdx.x & 3;
    const int tid  = threadIdx.x;
    const int lane = tid & 31;
    const int wid  = tid >> 5;

    const uint32_t exchS_addr = s2u(exchS);
    const uint32_t exchC_addr = s2u(exchC);

    const float* embT = g_embT + (size_t)b * Hc * NRc;

    for (int t = tid; t < 12288 / 4; t += STH)
        *reinterpret_cast<float4*>(&Wcs[t*4]) = *reinterpret_cast<const float4*>(Wc + t*4);
    // cache emb slice columns [0, NCACHE) for all 64 k
    for (int t = tid; t < 64 * NCACHE / 4; t += STH) {
        int k = t / (NCACHE / 4);
        int n4 = (t % (NCACHE / 4)) * 4;
        *reinterpret_cast<float4*>(&embc[k * NCACHE + n4]) =
            *reinterpret_cast<const float4*>(embT + (size_t)k * NRc + rank * RPC + n4);
    }
    if (tid < 128) ctxs[tid] = contexts[b * DCTX + tid];
    if (tid < 64)  { bcs[tid] = bc[tid]; float iv = init_emb[tid]; hist[tid] = iv; cur[tid] = iv; }
    if (tid == 0)  scal[0] = 0.0f;
    __syncthreads();
    CLUSTER_SYNC();

    for (int step = 0; step < Ac; step++) {
        // ---- hist = layernorm(hist + cur)
        if (tid < 64) tmp[tid] = hist[tid] + cur[tid];
        if (tid == 0) seli[0] = 0x7fffffff;
        __syncthreads();
        if (wid == 0) {
            float x0 = tmp[lane], x1 = tmp[lane + 32];
            float s = x0 + x1;
#pragma unroll
            for (int off = 16; off > 0; off >>= 1) s += __shfl_xor_sync(0xffffffffu, s, off);
            float mean = s * (1.0f / 64.0f);
            float d0 = x0 - mean, d1 = x1 - mean;
            float vs = d0*d0 + d1*d1;
#pragma unroll
            for (int off = 16; off > 0; off >>= 1) vs += __shfl_xor_sync(0xffffffffu, vs, off);
            if (lane == 0) {
                scal[1] = mean;
                scal[2] = 1.0f / sqrtf(vs * (1.0f / 64.0f) + 1e-5f);
            }
        }
        __syncthreads();
        if (tid < 64) hist[tid] = (tmp[tid] - scal[1]) * scal[2];
        __syncthreads();

        // ---- c = concat(ctx, hist) @ Wc + bc (8-way split), then normalize
        {
            int col = tid & 63, part = tid >> 6;      // 8 parts x 24 rows
            int i0 = part * 24;
            float s = 0.0f;
#pragma unroll 8
            for (int i = i0; i < i0 + 24; i++) {
                float x = (i < 128) ? ctxs[i] : hist[i - 128];
                s = fmaf(x, Wcs[i*64 + col], s);
            }
            cpart[part * 64 + col] = s;
        }
        __syncthreads();
        if (tid < 64) {
            float s = bcs[tid];
#pragma unroll
            for (int p = 0; p < 8; p++) s += cpart[p*64 + tid];
            cvec[tid] = s;
        }
        __syncthreads();
        if (wid == 0) {
            float c0 = cvec[lane], c1 = cvec[lane + 32];
            float ss = c0*c0 + c1*c1;
#pragma unroll
            for (int off = 16; off > 0; off >>= 1) ss += __shfl_xor_sync(0xffffffffu, ss, off);
            if (lane == 0) scal[3] = 1.0f / fmaxf(sqrtf(ss), 1e-12f);
        }
        __syncthreads();
        if (tid < 64) cvec[tid] *= scal[3];
        __syncthreads();

        // ---- scores e = exp(emb@c)  (unit vectors: |score|<=1, no max pass)
        float sx = 0.f, sy = 0.f;
        if (tid < NCACHE / 2) {
            const float* ep = embc + 2 * tid;
#pragma unroll 8
            for (int k = 0; k < 64; k++) {
                float2 v = *reinterpret_cast<const float2*>(ep + k * NCACHE);
                float ck = cvec[k];
                sx = fmaf(v.x, ck, sx); sy = fmaf(v.y, ck, sy);
            }
        } else {
            const float* ep = embT + rank * RPC + 2 * tid;
#pragma unroll 8
            for (int k = 0; k < 64; k++) {
                float2 v = *reinterpret_cast<const float2*>(ep + (size_t)k * NRc);
                float ck = cvec[k];
                sx = fmaf(v.x, ck, sx); sy = fmaf(v.y, ck, sy);
            }
        }
        float e0 = expf(sx), e1 = expf(sy);
        float t2 = e0 + e1;

        // ---- intra-CTA prefix of per-thread totals (16 warps)
        float incl = t2;
#pragma unroll
        for (int off = 1; off < 32; off <<= 1) {
            float n = __shfl_up_sync(0xffffffffu, incl, off);
            if (lane >= off) incl += n;
        }
        if (lane == 31) wred[wid] = incl;
        __syncthreads();
        if (tid == 0) {
            float s = 0.0f;
#pragma unroll
            for (int w = 0; w < 16; w++) { float v = wred[w]; wexc[w] = s; s += v; }
            scal[4] = s;
        }
        __syncthreads();
        float S_local  = scal[4];
        float excl_thr = wexc[wid] + (incl - t2);

        // ---- cluster: share local sums
        if (tid < CL) st_cluster_f32(exchS_addr + (uint32_t)rank * 4u, (uint32_t)tid, S_local);
        CLUSTER_SYNC();
        float S_tot = 0.0f, pre = 0.0f;
#pragma unroll
        for (int r = 0; r < CL; r++) {
            float v = exchS[r];
            if (r < rank) pre += v;
            S_tot += v;
        }

        // ---- selection: first global index with cumsum(e) > r * S_tot
        float T = rand_vals[b * Ac + step] * S_tot;
        float base = pre + excl_thr;
        int cand = 0x7fffffff;
        int gr = rank * RPC + tid * 2;
        if      (base + e0 > T) cand = gr;
        else if (base + t2 > T) cand = gr + 1;
        if (cand != 0x7fffffff) atomicMin(seli, cand);
        __syncthreads();
        int lc = seli[0];
        if (tid < CL) st_cluster_u32(exchC_addr + (uint32_t)rank * 4u, (uint32_t)tid, (uint32_t)lc);
        CLUSTER_SYNC();
        int sel = 0x7fffffff;
#pragma unroll
        for (int r = 0; r < CL; r++) sel = min(sel, exchC[r]);
        if (sel == 0x7fffffff) sel = 0;

        // ---- cur = emb[sel]; lp += score_sel - log(S_tot)
        if (tid < 64) cur[tid] = embT[(size_t)tid * NRc + sel];
        __syncthreads();
        if (wid == 0) {
            float d = cur[lane] * cvec[lane] + cur[lane + 32] * cvec[lane + 32];
#pragma unroll
            for (int off = 16; off > 0; off >>= 1) d += __shfl_xor_sync(0xffffffffu, d, off);
            if (lane == 0) scal[0] += d - logf(S_tot);
        }
        if (rank == 0 && tid == 0) out[b * Ac + step] = (float)sel;
        __syncthreads();
    }

    if (rank == 0 && tid == 0) out[Bc*Ac + b] = scal[0];
    if (rank == 0 && tid < 64) out[Bc*Ac + Bc + b*Hc + tid] = hist[tid];
    CLUSTER_SYNC();
}

// ---------------- launcher ----------------
extern "C" void kernel_launch(void* const* d_in, const int* in_sizes, int n_in,
                              void* d_out, int out_size) {
    const float* roles     = (const float*)d_in[0];
    const float* contexts  = (const float*)d_in[1];
    const float* eps       = (const float*)d_in[2];
    const float* rand_vals = (const float*)d_in[3];
    const float* W1  = (const float*)d_in[5];
    const float* b1  = (const float*)d_in[6];
    const float* W21 = (const float*)d_in[7];
    const float* b21 = (const float*)d_in[8];
    const float* W22 = (const float*)d_in[9];
    const float* b22 = (const float*)d_in[10];
    const float* W3  = (const float*)d_in[11];
    const float* b3  = (const float*)d_in[12];
    const float* W4  = (const float*)d_in[13];
    const float* b4  = (const float*)d_in[14];
    const float* Wc  = (const float*)d_in[15];
    const float* bc  = (const float*)d_in[16];
    const float* init_emb = (const float*)d_in[17];
    float* out = (float*)d_out;

    const int vae_smem  = VAE_SMEM_FLOATS  * (int)sizeof(float);
    const int scan_smem = SCAN_SMEM_FLOATS * (int)sizeof(float);
    cudaFuncSetAttribute(vae_kernel,  cudaFuncAttributeMaxDynamicSharedMemorySize, vae_smem);
    cudaFuncSetAttribute(scan_kernel, cudaFuncAttributeMaxDynamicSharedMemorySize, scan_smem);

    zero_kernel<<<1, 32>>>();
    vae_kernel<<<MTOT / 128, 256, vae_smem>>>(roles, eps, W1, b1, W21, b21,
                                              W22, b22, W3, b3, W4, b4);
    finalize_kernel<<<1, 1>>>(out);
    scan_kernel<<<Bc * CL, STH, scan_smem>>>(contexts, rand_vals, Wc, bc,
                                             init_emb, out);
}

// round 4
// speedup vs baseline: 1.5721x; 1.0693x over previous
#include <cuda_runtime.h>
#include <math.h>
#include <stdint.h>

// ---------------- problem constants ----------------
#define Bc   32
#define NRc  4096
#define DIN  384
#define DCTX 128
#define Hc   64
#define Ac   16
#define MTOT (Bc * NRc)

#define LOG_VAR2_C  (-4.6051701859880914f)
#define INV_VAR2_C  (100.0f)
#define STD2_C      (0.1f)

// ---------------- device scratch ----------------
__device__ float g_embT[(size_t)Bc * Hc * NRc];   // [b][k][n]
__device__ float g_mse[Bc];
__device__ float g_kld[Bc];

// ---------------- zero accumulators ----------------
__global__ void zero_kernel() {
    int t = threadIdx.x;
    if (t < Bc) { g_mse[t] = 0.0f; g_kld[t] = 0.0f; }
}

// ---------------- fused VAE kernel (proven ~390us, unchanged) ----------------
#define VAE_SMEM_FLOATS (16*128 + 16*64 + 128*65 + 64*64 + 64 + 128)

__global__ __launch_bounds__(256, 2)
void vae_kernel(const float* __restrict__ roles, const float* __restrict__ eps,
                const float* __restrict__ W1,  const float* __restrict__ b1,
                const float* __restrict__ W21, const float* __restrict__ b21,
                const float* __restrict__ W22, const float* __restrict__ b22,
                const float* __restrict__ W3,  const float* __restrict__ b3,
                const float* __restrict__ W4,  const float* __restrict__ b4)
{
    extern __shared__ float sm[];
    float* As  = sm;
    float* Bs  = As + 16*128;
    float* Hs  = Bs + 16*64;
    float* Ws  = Hs + 128*65;
    float* red = Ws + 64*64;
    float* rns = red + 64;

    const int tid  = threadIdx.x;
    const int tcol = tid & 15;
    const int trow = tid >> 4;
    const int row0 = blockIdx.x * 128;
    const int b    = row0 >> 12;

    float acc[8][4];

#pragma unroll
    for (int i = 0; i < 8; i++)
#pragma unroll
        for (int j = 0; j < 4; j++) acc[i][j] = 0.0f;

    for (int kt = 0; kt < DIN; kt += 16) {
#pragma unroll
        for (int q = 0; q < 2; q++) {
            int f  = tid + q * 256;
            int m  = f >> 2;
            int k4 = (f & 3) * 4;
            float4 v = *reinterpret_cast<const float4*>(
                roles + (size_t)(row0 + m) * DIN + kt + k4);
            As[(k4 + 0) * 128 + m] = v.x;
            As[(k4 + 1) * 128 + m] = v.y;
            As[(k4 + 2) * 128 + m] = v.z;
            As[(k4 + 3) * 128 + m] = v.w;
        }
        {
            int k  = tid >> 4;
            int j4 = (tid & 15) * 4;
            *reinterpret_cast<float4*>(&Bs[k * 64 + j4]) =
                *reinterpret_cast<const float4*>(W1 + (size_t)(kt + k) * Hc + j4);
        }
        __syncthreads();
#pragma unroll
        for (int k = 0; k < 16; k++) {
            float a[8];
            *reinterpret_cast<float4*>(&a[0]) = *reinterpret_cast<float4*>(&As[k*128 + trow*8]);
            *reinterpret_cast<float4*>(&a[4]) = *reinterpret_cast<float4*>(&As[k*128 + trow*8 + 4]);
            float4 bb = *reinterpret_cast<float4*>(&Bs[k*64 + tcol*4]);
#pragma unroll
            for (int i = 0; i < 8; i++) {
                acc[i][0] += a[i] * bb.x;
                acc[i][1] += a[i] * bb.y;
                acc[i][2] += a[i] * bb.z;
                acc[i][3] += a[i] * bb.w;
            }
        }
        __syncthreads();
    }
    {
        float4 bv = *reinterpret_cast<const float4*>(b1 + tcol * 4);
#pragma unroll
        for (int i = 0; i < 8; i++) {
            int r = trow * 8 + i;
            Hs[r*65 + tcol*4 + 0] = fmaxf(acc[i][0] + bv.x, 0.0f);
            Hs[r*65 + tcol*4 + 1] = fmaxf(acc[i][1] + bv.y, 0.0f);
            Hs[r*65 + tcol*4 + 2] = fmaxf(acc[i][2] + bv.z, 0.0f);
            Hs[r*65 + tcol*4 + 3] = fmaxf(acc[i][3] + bv.w, 0.0f);
        }
    }
    for (int t = tid; t < 1024; t += 256)
        *reinterpret_cast<float4*>(&Ws[t*4]) = *reinterpret_cast<const float4*>(W22 + t*4);
    __syncthreads();

    float kacc = 0.0f;
    float sreg[8][4];

#pragma unroll
    for (int i = 0; i < 8; i++)
#pragma unroll
        for (int j = 0; j < 4; j++) acc[i][j] = 0.0f;
#pragma unroll 8
    for (int k = 0; k < 64; k++) {
        float a[8];
#pragma unroll
        for (int i = 0; i < 8; i++) a[i] = Hs[(trow*8 + i)*65 + k];
        float4 bb = *reinterpret_cast<float4*>(&Ws[k*64 + tcol*4]);
#pragma unroll
        for (int i = 0; i < 8; i++) {
            acc[i][0] += a[i]*bb.x; acc[i][1] += a[i]*bb.y;
            acc[i][2] += a[i]*bb.z; acc[i][3] += a[i]*bb.w;
        }
    }
    {
        float4 bv = *reinterpret_cast<const float4*>(b22 + tcol * 4);
#pragma unroll
        for (int i = 0; i < 8; i++) {
            float bvv[4] = {bv.x, bv.y, bv.z, bv.w};
#pragma unroll
            for (int j = 0; j < 4; j++) {
                float lv = acc[i][j] + bvv[j];
                float ex = expf(lv);
                kacc += (1.0f - LOG_VAR2_C + lv - ex * INV_VAR2_C);
                sreg[i][j] = expf(0.5f * lv) * STD2_C;
            }
        }
    }
    __syncthreads();
    for (int t = tid; t < 1024; t += 256)
        *reinterpret_cast<float4*>(&Ws[t*4]) = *reinterpret_cast<const float4*>(W21 + t*4);
    __syncthreads();

#pragma unroll
    for (int i = 0; i < 8; i++)
#pragma unroll
        for (int j = 0; j < 4; j++) acc[i][j] = 0.0f;
#pragma unroll 8
    for (int k = 0; k < 64; k++) {
        float a[8];
#pragma unroll
        for (int i = 0; i < 8; i++) a[i] = Hs[(trow*8 + i)*65 + k];
        float4 bb = *reinterpret_cast<float4*>(&Ws[k*64 + tcol*4]);
#pragma unroll
        for (int i = 0; i < 8; i++) {
            acc[i][0] += a[i]*bb.x; acc[i][1] += a[i]*bb.y;
            acc[i][2] += a[i]*bb.z; acc[i][3] += a[i]*bb.w;
        }
    }
    {
        float4 bv = *reinterpret_cast<const float4*>(b21 + tcol * 4);
        float bvv[4] = {bv.x, bv.y, bv.z, bv.w};
#pragma unroll
        for (int i = 0; i < 8; i++) {
            float4 ev = *reinterpret_cast<const float4*>(
                eps + (size_t)(row0 + trow*8 + i) * Hc + tcol * 4);
            float evv[4] = {ev.x, ev.y, ev.z, ev.w};
#pragma unroll
            for (int j = 0; j < 4; j++) {
                float mu = acc[i][j] + bvv[j];
                kacc -= mu * mu * INV_VAR2_C;
                acc[i][j] = mu + evv[j] * sreg[i][j];
            }
        }
    }
    __syncthreads();
#pragma unroll
    for (int i = 0; i < 8; i++) {
        int r = trow * 8 + i;
        Hs[r*65 + tcol*4 + 0] = acc[i][0];
        Hs[r*65 + tcol*4 + 1] = acc[i][1];
        Hs[r*65 + tcol*4 + 2] = acc[i][2];
        Hs[r*65 + tcol*4 + 3] = acc[i][3];
    }
    for (int t = tid; t < 1024; t += 256)
        *reinterpret_cast<float4*>(&Ws[t*4]) = *reinterpret_cast<const float4*>(W3 + t*4);
    __syncthreads();

    if (tid < 128) {
        float ss = 0.0f;
#pragma unroll
        for (int k = 0; k < 64; k++) { float v = Hs[tid*65 + k]; ss += v * v; }
        rns[tid] = 1.0f / fmaxf(sqrtf(ss), 1e-12f);
    }
    __syncthreads();
    {
        const int nloc0 = row0 & (NRc - 1);
        for (int t = tid; t < 128 * 64; t += 256) {
            int k = t >> 7;
            int r = t & 127;
            g_embT[((size_t)b * Hc + k) * NRc + nloc0 + r] = Hs[r*65 + k] * rns[r];
        }
    }

#pragma unroll
    for (int i = 0; i < 8; i++)
#pragma unroll
        for (int j = 0; j < 4; j++) acc[i][j] = 0.0f;
#pragma unroll 8
    for (int k = 0; k < 64; k++) {
        float a[8];
#pragma unroll
        for (int i = 0; i < 8; i++) a[i] = Hs[(trow*8 + i)*65 + k];
        float4 bb = *reinterpret_cast<float4*>(&Ws[k*64 + tcol*4]);
#pragma unroll
        for (int i = 0; i < 8; i++) {
            acc[i][0] += a[i]*bb.x; acc[i][1] += a[i]*bb.y;
            acc[i][2] += a[i]*bb.z; acc[i][3] += a[i]*bb.w;
        }
    }
    {
        float4 bv = *reinterpret_cast<const float4*>(b3 + tcol * 4);
        float bvv[4] = {bv.x, bv.y, bv.z, bv.w};
#pragma unroll
        for (int i = 0; i < 8; i++)
#pragma unroll
            for (int j = 0; j < 4; j++)
                acc[i][j] = fmaxf(acc[i][j] + bvv[j], 0.0f);
    }
    __syncthreads();
#pragma unroll
    for (int i = 0; i < 8; i++) {
        int r = trow * 8 + i;
        Hs[r*65 + tcol*4 + 0] = acc[i][0];
        Hs[r*65 + tcol*4 + 1] = acc[i][1];
        Hs[r*65 + tcol*4 + 2] = acc[i][2];
        Hs[r*65 + tcol*4 + 3] = acc[i][3];
    }

    float msacc = 0.0f;
    for (int ch = 0; ch < 6; ch++) {
        for (int t = tid; t < 1024; t += 256) {
            int k  = t >> 4;
            int j4 = (t & 15) * 4;
            *reinterpret_cast<float4*>(&Ws[k*64 + j4]) =
                *reinterpret_cast<const float4*>(W4 + (size_t)k * DIN + ch * 64 + j4);
        }
        __syncthreads();
#pragma unroll
        for (int i = 0; i < 8; i++)
#pragma unroll
            for (int j = 0; j < 4; j++) acc[i][j] = 0.0f;
#pragma unroll 8
        for (int k = 0; k < 64; k++) {
            float a[8];
#pragma unroll
            for (int i = 0; i < 8; i++) a[i] = Hs[(trow*8 + i)*65 + k];
            float4 bb = *reinterpret_cast<float4*>(&Ws[k*64 + tcol*4]);
#pragma unroll
            for (int i = 0; i < 8; i++) {
                acc[i][0] += a[i]*bb.x; acc[i][1] += a[i]*bb.y;
                acc[i][2] += a[i]*bb.z; acc[i][3] += a[i]*bb.w;
            }
        }
        {
            float4 bv = *reinterpret_cast<const float4*>(b4 + ch * 64 + tcol * 4);
            float bvv[4] = {bv.x, bv.y, bv.z, bv.w};
#pragma unroll
            for (int i = 0; i < 8; i++) {
                float4 rv = *reinterpret_cast<const float4*>(
                    roles + (size_t)(row0 + trow*8 + i) * DIN + ch * 64 + tcol * 4);
                float rvv[4] = {rv.x, rv.y, rv.z, rv.w};
#pragma unroll
                for (int j = 0; j < 4; j++) {
                    float d = acc[i][j] + bvv[j] - rvv[j];
                    msacc += d * d;
                }
            }
        }
        __syncthreads();
    }

    float ks = kacc, ms = msacc;
#pragma unroll
    for (int off = 16; off > 0; off >>= 1) {
        ks += __shfl_xor_sync(0xffffffffu, ks, off);
        ms += __shfl_xor_sync(0xffffffffu, ms, off);
    }
    if ((tid & 31) == 0) { red[tid >> 5] = ks; red[8 + (tid >> 5)] = ms; }
    __syncthreads();
    if (tid == 0) {
        float kt = 0.0f, mt = 0.0f;
#pragma unroll
        for (int w = 0; w < 8; w++) { kt += red[w]; mt += red[8 + w]; }
        atomicAdd(&g_kld[b], kt);
        atomicAdd(&g_mse[b], mt);
    }
}

// ---------------- vae loss finalize ----------------
__global__ void finalize_kernel(float* __restrict__ out) {
    if (threadIdx.x == 0) {
        float v = 0.0f;
        for (int b = 0; b < Bc; b++) {
            float mse = g_mse[b] * (1.0f / ((float)NRc * (float)DIN));
            float kld = (-0.5f / ((float)NRc * (float)Hc)) * g_kld[b];
            v += mse + kld;
        }
        out[Bc*Ac + Bc + Bc*Hc] = v / (float)Bc;
    }
}

// ---------------- cluster / mbarrier helpers ----------------
__device__ __forceinline__ uint32_t s2u(const void* p) {
    uint32_t a;
    asm("{ .reg .u64 t; cvta.to.shared.u64 t, %1; cvt.u32.u64 %0, t; }" : "=r"(a) : "l"(p));
    return a;
}
__device__ __forceinline__ void mbar_init(uint32_t mbar, uint32_t cnt) {
    asm volatile("mbarrier.init.shared.b64 [%0], %1;" :: "r"(mbar), "r"(cnt) : "memory");
}
__device__ __forceinline__ void mbar_expect_tx(uint32_t mbar, uint32_t bytes) {
    asm volatile("mbarrier.arrive.expect_tx.shared.b64 _, [%0], %1;"
                 :: "r"(mbar), "r"(bytes) : "memory");
}
// store 4B into peer CTA's smem slot, signaling peer's mbarrier via complete_tx
__device__ __forceinline__ void st_async_b32(uint32_t slot, uint32_t mbar,
                                             uint32_t peer, uint32_t val) {
    uint32_t rs, rb;
    asm("mapa.shared::cluster.u32 %0, %1, %2;" : "=r"(rs) : "r"(slot), "r"(peer));
    asm("mapa.shared::cluster.u32 %0, %1, %2;" : "=r"(rb) : "r"(mbar), "r"(peer));
    asm volatile("st.async.shared::cluster.mbarrier::complete_tx::bytes.b32 [%0], %1, [%2];"
                 :: "r"(rs), "r"(val), "r"(rb) : "memory");
}
__device__ __forceinline__ void mbar_wait_cluster(uint32_t mbar, uint32_t parity) {
    uint32_t done;
    asm volatile("{\n\t.reg .pred p;\n\t"
        "mbarrier.try_wait.parity.acquire.cluster.shared::cta.b64 p, [%1], %2;\n\t"
        "selp.b32 %0, 1, 0, p;\n\t}"
        : "=r"(done) : "r"(mbar), "r"(parity) : "memory");
    while (!done) {
        asm volatile("{\n\t.reg .pred p;\n\t"
            "mbarrier.try_wait.parity.acquire.cluster.shared::cta.b64 p, [%1], %2, 0x989680;\n\t"
            "selp.b32 %0, 1, 0, p;\n\t}"
            : "=r"(done) : "r"(mbar), "r"(parity) : "memory");
    }
}
#define CLUSTER_SYNC() do { \
    asm volatile("barrier.cluster.arrive.aligned;" ::: "memory"); \
    asm volatile("barrier.cluster.wait.aligned;"   ::: "memory"); } while (0)

// ---------------- cluster-parallel selection scan ----------------
// CL=4 CTAs per batch item, 512 threads each; thread owns 2 consecutive rows.
// Cross-CTA coordination via st.async + mbarrier (no barrier.cluster in the
// steady state -> no per-step L1D flush). Wc lives in registers (24/thread).
#define CL 4
#define STH 512
#define RPC (NRc / CL)           // 1024 rows per CTA
#define NCACHE 768               // rows of the slice cached in smem
// header: mbar[2](4f) exchS[2][4](8) exchC[2][4](8) seli(1) scal(7) wred(16)
//         wexc(16) ctxs(128) bcs(64) hist(64) cur(64) tmp(64) cvec(64) cpart(512)
//         = 1020 -> pad 1024 ; embc 64*NCACHE
#define SCAN_SMEM_FLOATS (1024 + 64*NCACHE)

__global__ __launch_bounds__(STH, 1) __cluster_dims__(CL, 1, 1)
void scan_kernel(const float* __restrict__ contexts, const float* __restrict__ rand_vals,
                 const float* __restrict__ Wc, const float* __restrict__ bc,
                 const float* __restrict__ init_emb, float* __restrict__ out)
{
    extern __shared__ float sm[];
    unsigned long long* mbar = (unsigned long long*)sm;  // [0]=S, [1]=C
    float* exchS = sm + 4;               // [2][4]
    int*   exchC = (int*)(sm + 12);      // [2][4]
    int*   seli  = (int*)(sm + 20);
    float* scal  = sm + 21;              // [0]=lp 1=mean 2=invstd 3=cnorm 4=S_local
    float* wred  = sm + 28;              // 16
    float* wexc  = sm + 44;              // 16
    float* ctxs  = sm + 60;              // 128
    float* bcs   = sm + 188;             // 64
    float* hist  = sm + 252;             // 64
    float* cur   = sm + 316;             // 64
    float* tmp   = sm + 380;             // 64
    float* cvec  = sm + 444;             // 64
    float* cpart = sm + 508;             // 512
    float* embc  = sm + 1024;            // 64*NCACHE

    const int b    = blockIdx.x >> 2;
    const int rank = blockIdx.x & 3;
    const int tid  = threadIdx.x;
    const int lane = tid & 31;
    const int wid  = tid >> 5;

    const uint32_t mbarS_a = s2u(&mbar[0]);
    const uint32_t mbarC_a = s2u(&mbar[1]);

    const float* embT = g_embT + (size_t)b * Hc * NRc;

    // Wc rows for this thread in registers: part = tid>>6 owns rows [part*24, +24)
    const int col  = tid & 63;
    const int irow = (tid >> 6) * 24;
    float wreg[24];
#pragma unroll
    for (int i = 0; i < 24; i++) wreg[i] = Wc[(size_t)(irow + i) * 64 + col];

    // cache emb slice columns [0, NCACHE)
    for (int t = tid; t < 64 * NCACHE / 4; t += STH) {
        int k  = t / (NCACHE / 4);
        int n4 = (t % (NCACHE / 4)) * 4;
        *reinterpret_cast<float4*>(&embc[k * NCACHE + n4]) =
            *reinterpret_cast<const float4*>(embT + (size_t)k * NRc + rank * RPC + n4);
    }
    if (tid < 128) ctxs[tid] = contexts[b * DCTX + tid];
    if (tid < 64)  { bcs[tid] = bc[tid]; float iv = init_emb[tid]; hist[tid] = iv; cur[tid] = iv; }
    if (tid == 0)  {
        scal[0] = 0.0f;
        mbar_init(mbarS_a, 1);
        mbar_init(mbarC_a, 1);
    }
    __syncthreads();
    CLUSTER_SYNC();     // mbarriers visible cluster-wide before any st.async

    for (int step = 0; step < Ac; step++) {
        const uint32_t par = (uint32_t)(step & 1);
        const uint32_t slotS = s2u(&exchS[(step & 1) * 4 + rank]);
        const uint32_t slotC = s2u(&exchC[(step & 1) * 4 + rank]);

        // ---- step-start bookkeeping
        if (tid == 0) {
            mbar_expect_tx(mbarS_a, 16);
            mbar_expect_tx(mbarC_a, 16);
            seli[0] = 0x7fffffff;
        }
        // ---- hist = layernorm(hist + cur)
        if (tid < 64) tmp[tid] = hist[tid] + cur[tid];
        __syncthreads();
        if (wid == 0) {
            float x0 = tmp[lane], x1 = tmp[lane + 32];
            float s = x0 + x1;
#pragma unroll
            for (int off = 16; off > 0; off >>= 1) s += __shfl_xor_sync(0xffffffffu, s, off);
            float mean = s * (1.0f / 64.0f);
            float d0 = x0 - mean, d1 = x1 - mean;
            float vs = d0*d0 + d1*d1;
#pragma unroll
            for (int off = 16; off > 0; off >>= 1) vs += __shfl_xor_sync(0xffffffffu, vs, off);
            if (lane == 0) {
                scal[1] = mean;
                scal[2] = 1.0f / sqrtf(vs * (1.0f / 64.0f) + 1e-5f);
            }
        }
        __syncthreads();
        if (tid < 64) hist[tid] = (tmp[tid] - scal[1]) * scal[2];
        __syncthreads();

        // ---- c = concat(ctx, hist) @ Wc + bc (8-way split, Wc in regs)
        {
            float s = 0.0f;
#pragma unroll
            for (int i = 0; i < 24; i++) {
                int gi = irow + i;
                float x = (gi < 128) ? ctxs[gi] : hist[gi - 128];
                s = fmaf(x, wreg[i], s);
            }
            cpart[(tid >> 6) * 64 + col] = s;
        }
        __syncthreads();
        if (tid < 64) {
            float s = bcs[tid];
#pragma unroll
            for (int p = 0; p < 8; p++) s += cpart[p*64 + tid];
            cvec[tid] = s;
        }
        __syncthreads();
        if (wid == 0) {
            float c0 = cvec[lane], c1 = cvec[lane + 32];
            float ss = c0*c0 + c1*c1;
#pragma unroll
            for (int off = 16; off > 0; off >>= 1) ss += __shfl_xor_sync(0xffffffffu, ss, off);
            if (lane == 0) scal[3] = 1.0f / fmaxf(sqrtf(ss), 1e-12f);
        }
        __syncthreads();
        if (tid < 64) cvec[tid] *= scal[3];
        __syncthreads();

        // ---- scores e = exp(emb@c)  (unit vectors: |score|<=1, no max pass)
        float sx = 0.f, sy = 0.f;
        if (tid < NCACHE / 2) {
            const float* ep = embc + 2 * tid;
#pragma unroll 8
            for (int k = 0; k < 64; k++) {
                float2 v = *reinterpret_cast<const float2*>(ep + k * NCACHE);
                float ck = cvec[k];
                sx = fmaf(v.x, ck, sx); sy = fmaf(v.y, ck, sy);
            }
        } else {
            const float* ep = embT + rank * RPC + 2 * tid;
#pragma unroll 16
            for (int k = 0; k < 64; k++) {
                float2 v = *reinterpret_cast<const float2*>(ep + (size_t)k * NRc);
                float ck = cvec[k];
                sx = fmaf(v.x, ck, sx); sy = fmaf(v.y, ck, sy);
            }
        }
        float e0 = expf(sx), e1 = expf(sy);
        float t2 = e0 + e1;

        // ---- intra-CTA prefix of per-thread totals (16 warps)
        float incl = t2;
#pragma unroll
        for (int off = 1; off < 32; off <<= 1) {
            float n = __shfl_up_sync(0xffffffffu, incl, off);
            if (lane >= off) incl += n;
        }
        if (lane == 31) wred[wid] = incl;
        __syncthreads();
        if (tid == 0) {
            float s = 0.0f;
#pragma unroll
            for (int w = 0; w < 16; w++) { float v = wred[w]; wexc[w] = s; s += v; }
            scal[4] = s;
        }
        __syncthreads();
        float S_local  = scal[4];
        float excl_thr = wexc[wid] + (incl - t2);

        // ---- cluster exchange #1: local sums (st.async, no L1 flush)
        if (tid < CL) st_async_b32(slotS, mbarS_a, (uint32_t)tid, __float_as_uint(S_local));
        mbar_wait_cluster(mbarS_a, par);
        float S_tot = 0.0f, pre = 0.0f;
#pragma unroll
        for (int r = 0; r < CL; r++) {
            float v = exchS[(step & 1) * 4 + r];
            if (r < rank) pre += v;
            S_tot += v;
        }

        // ---- selection: first global index with cumsum(e) > r * S_tot
        float T = rand_vals[b * Ac + step] * S_tot;
        float base = pre + excl_thr;
        int cand = 0x7fffffff;
        int gr = rank * RPC + tid * 2;
        if      (base + e0 > T) cand = gr;
        else if (base + t2 > T) cand = gr + 1;
        if (cand != 0x7fffffff) atomicMin(seli, cand);
        __syncthreads();
        int lc = seli[0];
        // ---- cluster exchange #2: candidates
        if (tid < CL) st_async_b32(slotC, mbarC_a, (uint32_t)tid, (uint32_t)lc);
        mbar_wait_cluster(mbarC_a, par);
        int sel = 0x7fffffff;
#pragma unroll
        for (int r = 0; r < CL; r++) sel = min(sel, exchC[(step & 1) * 4 + r]);
        if (sel == 0x7fffffff) sel = 0;

        // ---- cur = emb[sel]; lp += score_sel - log(S_tot)
        if (tid < 64) cur[tid] = embT[(size_t)tid * NRc + sel];
        __syncthreads();
        if (wid == 0) {
            float d = cur[lane] * cvec[lane] + cur[lane + 32] * cvec[lane + 32];
#pragma unroll
            for (int off = 16; off > 0; off >>= 1) d += __shfl_xor_sync(0xffffffffu, d, off);
            if (lane == 0) scal[0] += d - logf(S_tot);
        }
        if (rank == 0 && tid == 0) out[b * Ac + step] = (float)sel;
        __syncthreads();
    }

    if (rank == 0 && tid == 0) out[Bc*Ac + b] = scal[0];
    if (rank == 0 && tid < 64) out[Bc*Ac + Bc + b*Hc + tid] = hist[tid];
    CLUSTER_SYNC();     // no CTA exits while peers might still target its smem
}

// ---------------- launcher ----------------
extern "C" void kernel_launch(void* const* d_in, const int* in_sizes, int n_in,
                              void* d_out, int out_size) {
    const float* roles     = (const float*)d_in[0];
    const float* contexts  = (const float*)d_in[1];
    const float* eps       = (const float*)d_in[2];
    const float* rand_vals = (const float*)d_in[3];
    const float* W1  = (const float*)d_in[5];
    const float* b1  = (const float*)d_in[6];
    const float* W21 = (const float*)d_in[7];
    const float* b21 = (const float*)d_in[8];
    const float* W22 = (const float*)d_in[9];
    const float* b22 = (const float*)d_in[10];
    const float* W3  = (const float*)d_in[11];
    const float* b3  = (const float*)d_in[12];
    const float* W4  = (const float*)d_in[13];
    const float* b4  = (const float*)d_in[14];
    const float* Wc  = (const float*)d_in[15];
    const float* bc  = (const float*)d_in[16];
    const float* init_emb = (const float*)d_in[17];
    float* out = (float*)d_out;

    const int vae_smem  = VAE_SMEM_FLOATS  * (int)sizeof(float);
    const int scan_smem = SCAN_SMEM_FLOATS * (int)sizeof(float);
    cudaFuncSetAttribute(vae_kernel,  cudaFuncAttributeMaxDynamicSharedMemorySize, vae_smem);
    cudaFuncSetAttribute(scan_kernel, cudaFuncAttributeMaxDynamicSharedMemorySize, scan_smem);

    zero_kernel<<<1, 32>>>();
    vae_kernel<<<MTOT / 128, 256, vae_smem>>>(roles, eps, W1, b1, W21, b21,
                                              W22, b22, W3, b3, W4, b4);
    finalize_kernel<<<1, 1>>>(out);
    scan_kernel<<<Bc * CL, STH, scan_smem>>>(contexts, rand_vals, Wc, bc,
                                             init_emb, out);
}